// round 3
// baseline (speedup 1.0000x reference)
#include <cuda_runtime.h>

// ============================================================================
// QCNN 8-qubit circuit — exact algebraic reduction, single fused kernel,
// barrier-free (per-warp W build in registers via shuffles).
//
// CNOTs only couple disjoint qubit pairs; <Z_0> depends only on the (0,1)
// 2-qubit subsystem. Parameterized gates are batch-independent -> the whole
// 3-layer 2-qubit circuit is one fixed 4x4 complex unitary W. Since the input
// state psi0 is REAL, z = psi0^T S psi0 with S = Re(W^H D W), D=diag(1,1,-1,-1)
// a real symmetric 4x4 matrix. Per element:
//   psi0 = (c0c1, c0s1, s0c1, s0s1),  c_w=cos(x_w/2), s_w=sin(x_w/2)
//   z    = psi0^T S psi0
//   out  = sigmoid(weight * z)
// ============================================================================

struct Cx { float re, im; };

__device__ __forceinline__ Cx cmul(Cx a, Cx b) {
    return { a.re * b.re - a.im * b.im, a.re * b.im + a.im * b.re };
}

// Per-warp: build W (lanes 0..15 own element (r,c)), then compute the real
// symmetric quadratic form S = Re(W^H D W) redundantly in every lane.
// Output: S[16] in registers of EVERY lane. No smem, no block barrier.
__device__ __forceinline__ void build_S(const float* __restrict__ params,
                                        float (&S)[4][4]) {
    const unsigned FULL = 0xFFFFFFFFu;
    int lane = threadIdx.x & 31;
    int r = (lane >> 2) & 3;
    int c = lane & 3;

    Cx w = { (r == c) ? 1.0f : 0.0f, 0.0f };

    #pragma unroll
    for (int l = 0; l < 3; l++) {
        // U[q] = Rz(g) Ry(b) Rz(a), computed redundantly by every lane.
        Cx U[2][2][2];
        #pragma unroll
        for (int q = 0; q < 2; q++) {
            float a = params[(l * 8 + q) * 3 + 0];
            float b = params[(l * 8 + q) * 3 + 1];
            float g = params[(l * 8 + q) * 3 + 2];
            float sb, cb;  __sincosf(0.5f * b, &sb, &cb);
            float sp, cp;  __sincosf(0.5f * (a + g), &sp, &cp);
            float sm, cm;  __sincosf(0.5f * (a - g), &sm, &cm);
            U[q][0][0] = {  cb * cp, -cb * sp };
            U[q][0][1] = { -sb * cm, -sb * sm };
            U[q][1][0] = {  sb * cm, -sb * sm };
            U[q][1][1] = {  cb * cp,  cb * sp };
        }

        // K row r of (U0 (x) U1)
        Cx K[4];
        #pragma unroll
        for (int k = 0; k < 4; k++)
            K[k] = cmul(U[0][r >> 1][k >> 1], U[1][r & 1][k & 1]);

        // T[r][c] = sum_k K[r][k] * W[k][c]  (W[k][c] lives in lane k*4+c)
        Cx acc = { 0.0f, 0.0f };
        #pragma unroll
        for (int k = 0; k < 4; k++) {
            Cx wk;
            wk.re = __shfl_sync(FULL, w.re, k * 4 + c);
            wk.im = __shfl_sync(FULL, w.im, k * 4 + c);
            Cx p = cmul(K[k], wk);
            acc.re += p.re;  acc.im += p.im;
        }

        // CNOT(wire0->wire1): swap rows 2<->3.
        int sr = (r >= 2) ? (5 - r) : r;   // 0,1,3,2
        w.re = __shfl_sync(FULL, acc.re, sr * 4 + c);
        w.im = __shfl_sync(FULL, acc.im, sr * 4 + c);
    }

    // Broadcast the full W to every lane.
    float Wre[4][4], Wim[4][4];
    #pragma unroll
    for (int k = 0; k < 16; k++) {
        Wre[k >> 2][k & 3] = __shfl_sync(FULL, w.re, k);
        Wim[k >> 2][k & 3] = __shfl_sync(FULL, w.im, k);
    }

    // S[c][c2] = sum_r d_r * Re(conj(W[r][c]) W[r][c2]),  d = (1,1,-1,-1)
    #pragma unroll
    for (int a = 0; a < 4; a++)
        #pragma unroll
        for (int b = 0; b < 4; b++) {
            float s = 0.0f;
            #pragma unroll
            for (int rr = 0; rr < 4; rr++) {
                float t = fmaf(Wre[rr][a], Wre[rr][b], Wim[rr][a] * Wim[rr][b]);
                s += (rr < 2) ? t : -t;
            }
            S[a][b] = s;
        }
}

__device__ __forceinline__ float quad_form(const float (&S)[4][4], float2 xv) {
    float s0, c0, s1, c1;
    __sincosf(0.5f * xv.x, &s0, &c0);
    __sincosf(0.5f * xv.y, &s1, &c1);
    float psi[4] = { c0 * c1, c0 * s1, s0 * c1, s0 * s1 };

    float z = 0.0f;
    #pragma unroll
    for (int a = 0; a < 4; a++) {
        float t = 0.0f;
        #pragma unroll
        for (int b = 0; b < 4; b++)
            t = fmaf(S[a][b], psi[b], t);
        z = fmaf(psi[a], t, z);
    }
    return z;
}

__global__ void __launch_bounds__(128) qcnn_fused_kernel(
    const float* __restrict__ x,
    const float* __restrict__ params,
    const float* __restrict__ weight,
    float* __restrict__ out,
    int n)
{
    int half = n >> 1;
    int i0 = blockIdx.x * blockDim.x + threadIdx.x;
    int i1 = i0 + half;

    // Issue both independent global loads FIRST (MLP=2), overlapping the
    // W/S build latency below.
    float2 xv0 = make_float2(0.0f, 0.0f);
    float2 xv1 = make_float2(0.0f, 0.0f);
    if (i0 < half) {
        xv0 = *reinterpret_cast<const float2*>(x + (size_t)i0 * 8);
        xv1 = *reinterpret_cast<const float2*>(x + (size_t)i1 * 8);
    }
    float wgt = __ldg(weight);

    // Per-warp, barrier-free build of the 4x4 real symmetric form S.
    float S[4][4];
    build_S(params, S);

    if (i0 >= half) return;

    float z0 = quad_form(S, xv0);
    float z1 = quad_form(S, xv1);

    out[i0] = __fdividef(1.0f, 1.0f + __expf(-wgt * z0));
    out[i1] = __fdividef(1.0f, 1.0f + __expf(-wgt * z1));
}

extern "C" void kernel_launch(void* const* d_in, const int* in_sizes, int n_in,
                              void* d_out, int out_size) {
    const float* x      = (const float*)d_in[0];   // (65536, 8) fp32
    const float* params = (const float*)d_in[1];   // (3, 8, 3) fp32
    const float* weight = (const float*)d_in[2];   // scalar fp32
    float* out = (float*)d_out;                    // (65536,) fp32

    int n = in_sizes[0] / 8;                       // 65536
    int half = n >> 1;

    int threads = 128;
    int blocks = (half + threads - 1) / threads;   // 256 blocks
    qcnn_fused_kernel<<<blocks, threads>>>(x, params, weight, out, n);
}